// round 4
// baseline (speedup 1.0000x reference)
#include <cuda_runtime.h>
#include <cuda_bf16.h>
#include <cstdint>

#define DEV_INLINE __device__ __forceinline__

static constexpr int M_DIM = 8192;
static constexpr int N_DIM = 4096;
static constexpr int K_DIM = 4096;

static constexpr float FP8_MAX_F  = 448.0f;
static constexpr float AMAX_EPS_F = 1e-8f;
static constexpr float MOMENTUM_F = 0.95f;

// -------- scratch (allocation-free: device globals) --------
__device__ __align__(16) uint8_t g_xq[(size_t)M_DIM * K_DIM];   // 32 MB e4m3
__device__ __align__(16) uint8_t g_wq[(size_t)N_DIM * K_DIM];   // 16 MB e4m3
__device__ unsigned int g_amax_bits[2];

// ======================= helpers =======================
DEV_INLINE uint32_t smem_u32(const void* p) {
    uint32_t r;
    asm("{ .reg .u64 t; cvta.to.shared.u64 t, %1; cvt.u32.u64 %0, t; }" : "=r"(r) : "l"(p));
    return r;
}
DEV_INLINE void cp_async16(uint32_t smem, const void* gmem) {
    asm volatile("cp.async.cg.shared.global [%0], [%1], 16;\n" :: "r"(smem), "l"(gmem));
}
DEV_INLINE uint32_t sw128(uint32_t off) { return off ^ ((off >> 3) & 0x70); }

// fp8 e4m3 mma: D[16x8] += A[16x32] * B[32x8], fp32 accum. Base ISA (sm_89+).
DEV_INLINE void mma_fp8(float* c, const uint32_t* a, const uint32_t* b) {
    asm volatile(
        "mma.sync.aligned.m16n8k32.row.col.f32.e4m3.e4m3.f32 "
        "{%0,%1,%2,%3}, {%4,%5,%6,%7}, {%8,%9}, {%0,%1,%2,%3};"
        : "+f"(c[0]), "+f"(c[1]), "+f"(c[2]), "+f"(c[3])
        : "r"(a[0]), "r"(a[1]), "r"(a[2]), "r"(a[3]), "r"(b[0]), "r"(b[1]));
}

// ======================= kernel 0: init amax scratch =======================
__global__ void init_amax_kernel(unsigned int* bits) {
    if (threadIdx.x < 2) bits[threadIdx.x] = 0u;
}

// ======================= kernel 1: quantize + amax =======================
// 16 fp32 per thread -> 16 e4m3 bytes (in element order), block amax -> atomicMax.
__global__ void __launch_bounds__(256) quant_kernel(
    const float* __restrict__ in, uint8_t* __restrict__ outq,
    const float* __restrict__ amax_in, unsigned int* __restrict__ amax_bits)
{
    const int idx = blockIdx.x * blockDim.x + threadIdx.x;
    const float scale = FP8_MAX_F / fmaxf(__ldg(amax_in), AMAX_EPS_F);

    const float4* p = reinterpret_cast<const float4*>(in) + (size_t)idx * 4;
    float4 v0 = p[0], v1 = p[1], v2 = p[2], v3 = p[3];
    float vals[16] = {v0.x, v0.y, v0.z, v0.w, v1.x, v1.y, v1.z, v1.w,
                      v2.x, v2.y, v2.z, v2.w, v3.x, v3.y, v3.z, v3.w};

    float m = 0.0f;
    #pragma unroll
    for (int i = 0; i < 16; i++) m = fmaxf(m, fabsf(vals[i]));

    unsigned short h[8];
    #pragma unroll
    for (int i = 0; i < 8; i++) {
        // d = {hi: cvt(srcA), lo: cvt(srcB)} -> byte0 = element 2i, byte1 = element 2i+1
        asm("cvt.rn.satfinite.e4m3x2.f32 %0, %1, %2;"
            : "=h"(h[i]) : "f"(vals[2*i+1] * scale), "f"(vals[2*i] * scale));
    }
    uint4 outv;
    outv.x = (uint32_t)h[0] | ((uint32_t)h[1] << 16);
    outv.y = (uint32_t)h[2] | ((uint32_t)h[3] << 16);
    outv.z = (uint32_t)h[4] | ((uint32_t)h[5] << 16);
    outv.w = (uint32_t)h[6] | ((uint32_t)h[7] << 16);
    reinterpret_cast<uint4*>(outq)[idx] = outv;

    #pragma unroll
    for (int o = 16; o > 0; o >>= 1) m = fmaxf(m, __shfl_xor_sync(0xffffffff, m, o));
    __shared__ float wmax[8];
    if ((threadIdx.x & 31) == 0) wmax[threadIdx.x >> 5] = m;
    __syncthreads();
    if (threadIdx.x == 0) {
        float t = wmax[0];
        #pragma unroll
        for (int i = 1; i < 8; i++) t = fmaxf(t, wmax[i]);
        atomicMax(amax_bits, __float_as_uint(t));
    }
}

// ======================= kernel 2: amax EMA finalize =======================
__global__ void finalize_amax_kernel(
    const float* __restrict__ in_amax, const float* __restrict__ w_amax,
    const unsigned int* __restrict__ bits, float* __restrict__ tail)
{
    if (threadIdx.x == 0) {
        float ax = __uint_as_float(bits[0]);
        float aw = __uint_as_float(bits[1]);
        if (!(ax == ax)) ax = AMAX_EPS_F;
        if (isinf(ax))   ax = FP8_MAX_F;
        if (!(aw == aw)) aw = AMAX_EPS_F;
        if (isinf(aw))   aw = FP8_MAX_F;
        tail[0] = fmaxf(fmaxf(__ldg(in_amax) * MOMENTUM_F, ax), AMAX_EPS_F);
        tail[1] = fmaxf(fmaxf(__ldg(w_amax)  * MOMENTUM_F, aw), AMAX_EPS_F);
    }
}

// ======================= GEMM: fp8 mma.sync =======================
static constexpr int BM = 256, BN = 128, BK = 128, NSTAGE = 3;
static constexpr int NKT = K_DIM / BK;                 // 32
static constexpr int A_TILE_BYTES = BM * BK;           // 32768
static constexpr int B_TILE_BYTES = BN * BK;           // 16384
static constexpr int STAGE_BYTES  = A_TILE_BYTES + B_TILE_BYTES;  // 49152
static constexpr int SMEM_TOTAL   = NSTAGE * STAGE_BYTES;         // 147456

// one BK=128 slab of A(256 rows) + B(128 rows), SW128-swizzled, 512 threads
DEV_INLINE void load_stage(uint32_t sA, const uint8_t* gA, const uint8_t* gB,
                           int kt, int tid)
{
    const uint8_t* pA = gA + (size_t)kt * BK;
    const uint8_t* pB = gB + (size_t)kt * BK;
    #pragma unroll
    for (int i = 0; i < 4; i++) {                 // A: 2048 16B-chunks
        int chunk = tid + i * 512;
        int row = chunk >> 3, colb = (chunk & 7) << 4;
        cp_async16(sA + sw128((uint32_t)(row * BK + colb)),
                   pA + (size_t)row * K_DIM + colb);
    }
    const uint32_t sB = sA + A_TILE_BYTES;
    #pragma unroll
    for (int i = 0; i < 2; i++) {                 // B: 1024 16B-chunks
        int chunk = tid + i * 512;
        int row = chunk >> 3, colb = (chunk & 7) << 4;
        cp_async16(sB + sw128((uint32_t)(row * BK + colb)),
                   pB + (size_t)row * K_DIM + colb);
    }
    asm volatile("cp.async.commit_group;\n" ::: "memory");
}

__global__ void __launch_bounds__(512, 1)
gemm_kernel(float* __restrict__ out,
            const uint8_t* __restrict__ Aq, const uint8_t* __restrict__ Bq,
            const float* __restrict__ bias,
            const float* __restrict__ in_amax, const float* __restrict__ w_amax)
{
    extern __shared__ char smem[];
    const uint32_t sbase = smem_u32(smem);
    const int tid = threadIdx.x, wid = tid >> 5, lid = tid & 31;
    const int wm = wid >> 2, wn = wid & 3;         // 4x4 warp grid, tile 64x32
    const int bn = blockIdx.x, bm = blockIdx.y;

    const uint8_t* gA = Aq + (size_t)bm * BM * K_DIM;
    const uint8_t* gB = Bq + (size_t)bn * BN * K_DIM;

    float acc[4][4][4];
    #pragma unroll
    for (int mf = 0; mf < 4; mf++)
        #pragma unroll
        for (int nf = 0; nf < 4; nf++)
            #pragma unroll
            for (int q = 0; q < 4; q++) acc[mf][nf][q] = 0.0f;

    #pragma unroll
    for (int s = 0; s < NSTAGE; s++)
        load_stage(sbase + s * STAGE_BYTES, gA, gB, s, tid);

    const int q4 = (lid & 3) * 4;       // byte offset of this thread's k-quad
    const int rsub = lid >> 2;          // row/col within 8-group

    for (int kt = 0; kt < NKT; ++kt) {
        if (kt < NKT - 2)       asm volatile("cp.async.wait_group 2;\n" ::: "memory");
        else if (kt == NKT - 2) asm volatile("cp.async.wait_group 1;\n" ::: "memory");
        else                    asm volatile("cp.async.wait_group 0;\n" ::: "memory");
        __syncthreads();

        const char* stA = smem + (kt % NSTAGE) * STAGE_BYTES;
        const char* stB = stA + A_TILE_BYTES;

        #pragma unroll
        for (int ks = 0; ks < 4; ks++) {           // 4 x k32 within BK=128
            const int kb = ks * 32 + q4;
            uint32_t bfr[4][2];
            #pragma unroll
            for (int nf = 0; nf < 4; nf++) {
                const int n = wn * 32 + nf * 8 + rsub;
                const uint32_t off = (uint32_t)(n * BK + kb);
                bfr[nf][0] = *(const uint32_t*)(stB + sw128(off));
                bfr[nf][1] = *(const uint32_t*)(stB + sw128(off + 16));
            }
            #pragma unroll
            for (int mf = 0; mf < 4; mf++) {
                const int r0 = wm * 64 + mf * 16 + rsub;
                uint32_t a[4];
                const uint32_t off0 = (uint32_t)(r0 * BK + kb);
                const uint32_t off1 = off0 + 8 * BK;
                a[0] = *(const uint32_t*)(stA + sw128(off0));
                a[1] = *(const uint32_t*)(stA + sw128(off1));
                a[2] = *(const uint32_t*)(stA + sw128(off0 + 16));
                a[3] = *(const uint32_t*)(stA + sw128(off1 + 16));
                #pragma unroll
                for (int nf = 0; nf < 4; nf++) mma_fp8(acc[mf][nf], a, bfr[nf]);
            }
        }
        __syncthreads();
        if (kt + NSTAGE < NKT)
            load_stage(sbase + (kt % NSTAGE) * STAGE_BYTES, gA, gB, kt + NSTAGE, tid);
    }

    // ---- epilogue: D * (ax*aw/448^2) + bias ----
    const float ax = fmaxf(__ldg(in_amax), AMAX_EPS_F);
    const float aw = fmaxf(__ldg(w_amax), AMAX_EPS_F);
    const float inv = (ax * aw) * (1.0f / (FP8_MAX_F * FP8_MAX_F));

    #pragma unroll
    for (int mf = 0; mf < 4; mf++) {
        const int r0 = bm * BM + wm * 64 + mf * 16 + rsub;
        #pragma unroll
        for (int nf = 0; nf < 4; nf++) {
            const int col = bn * BN + wn * 32 + nf * 8 + (lid & 3) * 2;
            const float b0 = __ldg(bias + col), b1 = __ldg(bias + col + 1);
            float2 v0 = {acc[mf][nf][0] * inv + b0, acc[mf][nf][1] * inv + b1};
            float2 v1 = {acc[mf][nf][2] * inv + b0, acc[mf][nf][3] * inv + b1};
            *reinterpret_cast<float2*>(out + (size_t)r0 * N_DIM + col) = v0;
            *reinterpret_cast<float2*>(out + (size_t)(r0 + 8) * N_DIM + col) = v1;
        }
    }
}

// ======================= launch =======================
extern "C" void kernel_launch(void* const* d_in, const int* in_sizes, int n_in,
                              void* d_out, int out_size)
{
    const float* x       = (const float*)d_in[0];
    const float* w       = (const float*)d_in[1];
    const float* bias    = (const float*)d_in[2];
    const float* in_amax = (const float*)d_in[3];
    const float* w_amax  = (const float*)d_in[4];
    float* out = (float*)d_out;

    uint8_t *xq, *wq;
    unsigned int* ab;
    cudaGetSymbolAddress((void**)&xq, g_xq);
    cudaGetSymbolAddress((void**)&wq, g_wq);
    cudaGetSymbolAddress((void**)&ab, g_amax_bits);

    cudaFuncSetAttribute(gemm_kernel,
                         cudaFuncAttributeMaxDynamicSharedMemorySize, SMEM_TOTAL);

    init_amax_kernel<<<1, 32>>>(ab);
    quant_kernel<<<(M_DIM * K_DIM / 16) / 256, 256>>>(x, xq, in_amax, ab + 0);
    quant_kernel<<<(N_DIM * K_DIM / 16) / 256, 256>>>(w, wq, w_amax, ab + 1);
    finalize_amax_kernel<<<1, 32>>>(in_amax, w_amax, ab,
                                    out + (size_t)M_DIM * N_DIM);

    dim3 grid(N_DIM / BN, M_DIM / BM);   // (32, 32)
    gemm_kernel<<<grid, 512, SMEM_TOTAL>>>(out, xq, wq, bias, in_amax, w_amax);
}

// round 5
// speedup vs baseline: 1.2656x; 1.2656x over previous
#include <cuda_runtime.h>
#include <cuda_bf16.h>
#include <cstdint>

#define DEV_INLINE __device__ __forceinline__

static constexpr int M_DIM = 8192;
static constexpr int N_DIM = 4096;
static constexpr int K_DIM = 4096;
static constexpr int K_BYTES = K_DIM * 2;

static constexpr float FP8_MAX_F  = 448.0f;
static constexpr float AMAX_EPS_F = 1e-8f;
static constexpr float MOMENTUM_F = 0.95f;

// -------- scratch (allocation-free: device globals) --------
__device__ __align__(16) __nv_bfloat16 g_xq[(size_t)M_DIM * K_DIM];  // 64 MB
__device__ __align__(16) __nv_bfloat16 g_wq[(size_t)N_DIM * K_DIM];  // 32 MB
__device__ unsigned int g_amax_bits[2];

// ======================= helpers =======================
DEV_INLINE uint32_t smem_u32(const void* p) {
    uint32_t r;
    asm("{ .reg .u64 t; cvta.to.shared.u64 t, %1; cvt.u32.u64 %0, t; }" : "=r"(r) : "l"(p));
    return r;
}
DEV_INLINE void cp_async16(uint32_t smem, const void* gmem) {
    asm volatile("cp.async.cg.shared.global [%0], [%1], 16;\n" :: "r"(smem), "l"(gmem));
}
DEV_INLINE uint32_t sw128(uint32_t off) { return off ^ ((off >> 3) & 0x70); }

DEV_INLINE void ldsm_x4(uint32_t* r, uint32_t addr) {
    asm volatile("ldmatrix.sync.aligned.m8n8.x4.shared.b16 {%0,%1,%2,%3}, [%4];"
        : "=r"(r[0]), "=r"(r[1]), "=r"(r[2]), "=r"(r[3]) : "r"(addr));
}
DEV_INLINE void mma_bf16(float* c, const uint32_t* a, const uint32_t* b) {
    asm volatile(
        "mma.sync.aligned.m16n8k16.row.col.f32.bf16.bf16.f32 "
        "{%0,%1,%2,%3}, {%4,%5,%6,%7}, {%8,%9}, {%0,%1,%2,%3};"
        : "+f"(c[0]), "+f"(c[1]), "+f"(c[2]), "+f"(c[3])
        : "r"(a[0]), "r"(a[1]), "r"(a[2]), "r"(a[3]), "r"(b[0]), "r"(b[1]));
}

// ======================= kernel 0: init amax scratch =======================
__global__ void init_amax_kernel(unsigned int* bits) {
    if (threadIdx.x < 2) bits[threadIdx.x] = 0u;
}

// ======================= kernel 1: quantize + amax =======================
// fp32 -> scale -> e4m3 (rn.satfinite, exact ref semantics) -> bf16 (exact).
// Stores scaled-domain q values; epilogue multiplies by (ax*aw)/448^2.
__global__ void __launch_bounds__(256) quant_kernel(
    const float* __restrict__ in, __nv_bfloat16* __restrict__ outq,
    const float* __restrict__ amax_in, unsigned int* __restrict__ amax_bits)
{
    const int idx = blockIdx.x * blockDim.x + threadIdx.x;
    const float scale = FP8_MAX_F / fmaxf(__ldg(amax_in), AMAX_EPS_F);

    const float4* p = reinterpret_cast<const float4*>(in) + (size_t)idx * 2;
    float4 v0 = p[0], v1 = p[1];
    float vals[8] = {v0.x, v0.y, v0.z, v0.w, v1.x, v1.y, v1.z, v1.w};

    float m = 0.0f;
    #pragma unroll
    for (int i = 0; i < 8; i++) m = fmaxf(m, fabsf(vals[i]));

    uint32_t packed[4];
    #pragma unroll
    for (int i = 0; i < 4; i++) {
        unsigned short e;
        asm("cvt.rn.satfinite.e4m3x2.f32 %0, %1, %2;"
            : "=h"(e) : "f"(vals[2*i+1] * scale), "f"(vals[2*i] * scale));
        uint32_t h2;
        asm("cvt.rn.f16x2.e4m3x2 %0, %1;" : "=r"(h2) : "h"(e));
        float flo, fhi;
        asm("{ .reg .f16 a, b; mov.b32 {a, b}, %2; cvt.f32.f16 %0, a; cvt.f32.f16 %1, b; }"
            : "=f"(flo), "=f"(fhi) : "r"(h2));
        asm("cvt.rn.bf16x2.f32 %0, %1, %2;" : "=r"(packed[i]) : "f"(fhi), "f"(flo));
    }
    uint4 outv = {packed[0], packed[1], packed[2], packed[3]};
    reinterpret_cast<uint4*>(outq)[idx] = outv;

    #pragma unroll
    for (int o = 16; o > 0; o >>= 1) m = fmaxf(m, __shfl_xor_sync(0xffffffff, m, o));
    __shared__ float wmax[8];
    if ((threadIdx.x & 31) == 0) wmax[threadIdx.x >> 5] = m;
    __syncthreads();
    if (threadIdx.x == 0) {
        float t = wmax[0];
        #pragma unroll
        for (int i = 1; i < 8; i++) t = fmaxf(t, wmax[i]);
        atomicMax(amax_bits, __float_as_uint(t));
    }
}

// ======================= kernel 2: amax EMA finalize =======================
__global__ void finalize_amax_kernel(
    const float* __restrict__ in_amax, const float* __restrict__ w_amax,
    const unsigned int* __restrict__ bits, float* __restrict__ tail)
{
    if (threadIdx.x == 0) {
        float ax = __uint_as_float(bits[0]);
        float aw = __uint_as_float(bits[1]);
        if (!(ax == ax)) ax = AMAX_EPS_F;
        if (isinf(ax))   ax = FP8_MAX_F;
        if (!(aw == aw)) aw = AMAX_EPS_F;
        if (isinf(aw))   aw = FP8_MAX_F;
        tail[0] = fmaxf(fmaxf(__ldg(in_amax) * MOMENTUM_F, ax), AMAX_EPS_F);
        tail[1] = fmaxf(fmaxf(__ldg(w_amax)  * MOMENTUM_F, aw), AMAX_EPS_F);
    }
}

// ======================= GEMM: bf16 HMMA + ldmatrix =======================
static constexpr int BM = 128, BN = 256, BK = 64, NSTAGE = 3;
static constexpr int NKT = K_DIM / BK;                  // 64
static constexpr int ROWB = BK * 2;                     // 128 B per smem row
static constexpr int A_TILE_BYTES = BM * ROWB;          // 16384
static constexpr int B_TILE_BYTES = BN * ROWB;          // 32768
static constexpr int STAGE_BYTES  = A_TILE_BYTES + B_TILE_BYTES;  // 49152
static constexpr int SMEM_TOTAL   = NSTAGE * STAGE_BYTES;         // 147456

// one BK=64 slab of A(128 rows) + B(256 rows), SW128-swizzled, 512 threads
DEV_INLINE void load_stage(uint32_t sA, const __nv_bfloat16* gA,
                           const __nv_bfloat16* gB, int kt, int tid)
{
    const char* pA = (const char*)gA + (size_t)kt * ROWB;
    const char* pB = (const char*)gB + (size_t)kt * ROWB;
    #pragma unroll
    for (int i = 0; i < 2; i++) {                 // A: 1024 16B-chunks
        int chunk = tid + i * 512;
        int row = chunk >> 3, colb = (chunk & 7) << 4;
        cp_async16(sA + sw128((uint32_t)(row * ROWB + colb)),
                   pA + (size_t)row * K_BYTES + colb);
    }
    const uint32_t sB = sA + A_TILE_BYTES;
    #pragma unroll
    for (int i = 0; i < 4; i++) {                 // B: 2048 16B-chunks
        int chunk = tid + i * 512;
        int row = chunk >> 3, colb = (chunk & 7) << 4;
        cp_async16(sB + sw128((uint32_t)(row * ROWB + colb)),
                   pB + (size_t)row * K_BYTES + colb);
    }
    asm volatile("cp.async.commit_group;\n" ::: "memory");
}

__global__ void __launch_bounds__(512, 1)
gemm_kernel(float* __restrict__ out,
            const __nv_bfloat16* __restrict__ Aq, const __nv_bfloat16* __restrict__ Bq,
            const float* __restrict__ bias,
            const float* __restrict__ in_amax, const float* __restrict__ w_amax)
{
    extern __shared__ char smem[];
    const uint32_t sbase = smem_u32(smem);
    const int tid = threadIdx.x, wid = tid >> 5, lid = tid & 31;
    const int wm = wid >> 3, wn = wid & 7;        // 2x8 warp grid, tile 64x32
    const int bn = blockIdx.x, bm = blockIdx.y;

    const __nv_bfloat16* gA = Aq + (size_t)bm * BM * K_DIM;
    const __nv_bfloat16* gB = Bq + (size_t)bn * BN * K_DIM;

    float acc[4][4][4];
    #pragma unroll
    for (int mf = 0; mf < 4; mf++)
        #pragma unroll
        for (int nf = 0; nf < 4; nf++)
            #pragma unroll
            for (int q = 0; q < 4; q++) acc[mf][nf][q] = 0.0f;

    #pragma unroll
    for (int s = 0; s < NSTAGE; s++)
        load_stage(sbase + s * STAGE_BYTES, gA, gB, s, tid);

    // ldmatrix lane-address invariants
    // A x4 tiles: (m0-7,klo)(m8-15,klo)(m0-7,khi)(m8-15,khi) -> a0..a3
    const int a_row = wm * 64 + (lid & 7) + ((lid >> 3) & 1) * 8;   // + mf*16
    const int a_cbl = (lid >> 4) << 4;
    // B x4 tiles: (nf0,klo)(nf0,khi)(nf1,klo)(nf1,khi) -> b(nf0)lo,hi, b(nf1)lo,hi
    const int b_row = wn * 32 + ((lid >> 4) << 3) + (lid & 7);      // + p*16
    const int b_cbl = ((lid >> 3) & 1) << 4;

    for (int kt = 0; kt < NKT; ++kt) {
        if (kt < NKT - 2)       asm volatile("cp.async.wait_group 2;\n" ::: "memory");
        else if (kt == NKT - 2) asm volatile("cp.async.wait_group 1;\n" ::: "memory");
        else                    asm volatile("cp.async.wait_group 0;\n" ::: "memory");
        __syncthreads();

        const uint32_t stA = sbase + (kt % NSTAGE) * STAGE_BYTES;
        const uint32_t stB = stA + A_TILE_BYTES;

        #pragma unroll
        for (int ks = 0; ks < 4; ks++) {          // 4 x k16 within BK=64
            const int cb = ks * 32;
            uint32_t a[4][4], b[4][4];
            #pragma unroll
            for (int p = 0; p < 2; p++) {
                uint32_t off = (uint32_t)((b_row + p * 16) * ROWB + cb + b_cbl);
                ldsm_x4(b[p * 2], stB + sw128(off));   // fills b[2p][0..1]=nf2p, [2..3]->nf2p+1
            }
            #pragma unroll
            for (int mf = 0; mf < 4; mf++) {
                uint32_t off = (uint32_t)((a_row + mf * 16) * ROWB + cb + a_cbl);
                ldsm_x4(a[mf], stA + sw128(off));
            }
            #pragma unroll
            for (int mf = 0; mf < 4; mf++) {
                #pragma unroll
                for (int p = 0; p < 2; p++) {
                    mma_bf16(acc[mf][p * 2 + 0], a[mf], &b[p * 2][0]);
                    mma_bf16(acc[mf][p * 2 + 1], a[mf], &b[p * 2][2]);
                }
            }
        }
        __syncthreads();
        if (kt + NSTAGE < NKT)
            load_stage(sbase + (kt % NSTAGE) * STAGE_BYTES, gA, gB, kt + NSTAGE, tid);
    }

    // ---- epilogue: D * (ax*aw/448^2) + bias ----
    const float ax = fmaxf(__ldg(in_amax), AMAX_EPS_F);
    const float aw = fmaxf(__ldg(w_amax), AMAX_EPS_F);
    const float inv = (ax * aw) * (1.0f / (FP8_MAX_F * FP8_MAX_F));

    #pragma unroll
    for (int mf = 0; mf < 4; mf++) {
        const int r0 = bm * BM + wm * 64 + mf * 16 + (lid >> 2);
        #pragma unroll
        for (int nf = 0; nf < 4; nf++) {
            const int col = bn * BN + wn * 32 + nf * 8 + (lid & 3) * 2;
            const float b0 = __ldg(bias + col), b1 = __ldg(bias + col + 1);
            float2 v0 = {acc[mf][nf][0] * inv + b0, acc[mf][nf][1] * inv + b1};
            float2 v1 = {acc[mf][nf][2] * inv + b0, acc[mf][nf][3] * inv + b1};
            *reinterpret_cast<float2*>(out + (size_t)r0 * N_DIM + col) = v0;
            *reinterpret_cast<float2*>(out + (size_t)(r0 + 8) * N_DIM + col) = v1;
        }
    }
}

// ======================= launch =======================
extern "C" void kernel_launch(void* const* d_in, const int* in_sizes, int n_in,
                              void* d_out, int out_size)
{
    const float* x       = (const float*)d_in[0];
    const float* w       = (const float*)d_in[1];
    const float* bias    = (const float*)d_in[2];
    const float* in_amax = (const float*)d_in[3];
    const float* w_amax  = (const float*)d_in[4];
    float* out = (float*)d_out;

    __nv_bfloat16 *xq, *wq;
    unsigned int* ab;
    cudaGetSymbolAddress((void**)&xq, g_xq);
    cudaGetSymbolAddress((void**)&wq, g_wq);
    cudaGetSymbolAddress((void**)&ab, g_amax_bits);

    cudaFuncSetAttribute(gemm_kernel,
                         cudaFuncAttributeMaxDynamicSharedMemorySize, SMEM_TOTAL);

    init_amax_kernel<<<1, 32>>>(ab);
    quant_kernel<<<(M_DIM * K_DIM / 8) / 256, 256>>>(x, xq, in_amax, ab + 0);
    quant_kernel<<<(N_DIM * K_DIM / 8) / 256, 256>>>(w, wq, w_amax, ab + 1);
    finalize_amax_kernel<<<1, 32>>>(in_amax, w_amax, ab,
                                    out + (size_t)M_DIM * N_DIM);

    dim3 grid(N_DIM / BN, M_DIM / BM);   // (16, 64)
    gemm_kernel<<<grid, 512, SMEM_TOTAL>>>(out, xq, wq, bias, in_amax, w_amax);
}

// round 7
// speedup vs baseline: 1.3800x; 1.0904x over previous
#include <cuda_runtime.h>
#include <cuda_bf16.h>
#include <cstdint>

#define DEV_INLINE __device__ __forceinline__

static constexpr int M_DIM = 8192;
static constexpr int N_DIM = 4096;
static constexpr int K_DIM = 4096;
static constexpr int K_BYTES = K_DIM * 2;

static constexpr float FP8_MAX_F  = 448.0f;
static constexpr float AMAX_EPS_F = 1e-8f;
static constexpr float MOMENTUM_F = 0.95f;

// -------- scratch (allocation-free: device globals) --------
__device__ __align__(16) __nv_bfloat16 g_xq[(size_t)M_DIM * K_DIM];  // 64 MB
__device__ __align__(16) __nv_bfloat16 g_wq[(size_t)N_DIM * K_DIM];  // 32 MB
__device__ unsigned int g_amax_bits[2];

// ======================= helpers =======================
DEV_INLINE uint32_t smem_u32(const void* p) {
    uint32_t r;
    asm("{ .reg .u64 t; cvta.to.shared.u64 t, %1; cvt.u32.u64 %0, t; }" : "=r"(r) : "l"(p));
    return r;
}
DEV_INLINE void cp_async16(uint32_t smem, const void* gmem) {
    asm volatile("cp.async.cg.shared.global [%0], [%1], 16;\n" :: "r"(smem), "l"(gmem));
}
DEV_INLINE uint32_t sw128(uint32_t off) { return off ^ ((off >> 3) & 0x70); }

DEV_INLINE void ldsm_x4(uint32_t* r, uint32_t addr) {
    asm volatile("ldmatrix.sync.aligned.m8n8.x4.shared.b16 {%0,%1,%2,%3}, [%4];"
        : "=r"(r[0]), "=r"(r[1]), "=r"(r[2]), "=r"(r[3]) : "r"(addr));
}
DEV_INLINE void mma_bf16(float* c, const uint32_t* a, const uint32_t* b) {
    asm volatile(
        "mma.sync.aligned.m16n8k16.row.col.f32.bf16.bf16.f32 "
        "{%0,%1,%2,%3}, {%4,%5,%6,%7}, {%8,%9}, {%0,%1,%2,%3};"
        : "+f"(c[0]), "+f"(c[1]), "+f"(c[2]), "+f"(c[3])
        : "r"(a[0]), "r"(a[1]), "r"(a[2]), "r"(a[3]), "r"(b[0]), "r"(b[1]));
}

// ======================= kernel 0: init amax scratch =======================
__global__ void init_amax_kernel(unsigned int* bits) {
    if (threadIdx.x < 2) bits[threadIdx.x] = 0u;
}

// ======================= kernel 1: quantize + amax =======================
// fp32 -> scale -> e4m3 (rn.satfinite, exact ref semantics) -> bf16 (exact).
// Stores scaled-domain q values; epilogue multiplies by (ax*aw)/448^2.
__global__ void __launch_bounds__(256) quant_kernel(
    const float* __restrict__ in, __nv_bfloat16* __restrict__ outq,
    const float* __restrict__ amax_in, unsigned int* __restrict__ amax_bits)
{
    const int idx = blockIdx.x * blockDim.x + threadIdx.x;
    const float scale = FP8_MAX_F / fmaxf(__ldg(amax_in), AMAX_EPS_F);

    const float4* p = reinterpret_cast<const float4*>(in) + (size_t)idx * 2;
    float4 v0 = p[0], v1 = p[1];
    float vals[8] = {v0.x, v0.y, v0.z, v0.w, v1.x, v1.y, v1.z, v1.w};

    float m = 0.0f;
    #pragma unroll
    for (int i = 0; i < 8; i++) m = fmaxf(m, fabsf(vals[i]));

    uint32_t packed[4];
    #pragma unroll
    for (int i = 0; i < 4; i++) {
        unsigned short e;
        asm("cvt.rn.satfinite.e4m3x2.f32 %0, %1, %2;"
            : "=h"(e) : "f"(vals[2*i+1] * scale), "f"(vals[2*i] * scale));
        uint32_t h2;
        asm("cvt.rn.f16x2.e4m3x2 %0, %1;" : "=r"(h2) : "h"(e));
        float flo, fhi;
        asm("{ .reg .f16 a, b; mov.b32 {a, b}, %2; cvt.f32.f16 %0, a; cvt.f32.f16 %1, b; }"
            : "=f"(flo), "=f"(fhi) : "r"(h2));
        asm("cvt.rn.bf16x2.f32 %0, %1, %2;" : "=r"(packed[i]) : "f"(fhi), "f"(flo));
    }
    uint4 outv = {packed[0], packed[1], packed[2], packed[3]};
    reinterpret_cast<uint4*>(outq)[idx] = outv;

    #pragma unroll
    for (int o = 16; o > 0; o >>= 1) m = fmaxf(m, __shfl_xor_sync(0xffffffff, m, o));
    __shared__ float wmax[8];
    if ((threadIdx.x & 31) == 0) wmax[threadIdx.x >> 5] = m;
    __syncthreads();
    if (threadIdx.x == 0) {
        float t = wmax[0];
        #pragma unroll
        for (int i = 1; i < 8; i++) t = fmaxf(t, wmax[i]);
        atomicMax(amax_bits, __float_as_uint(t));
    }
}

// ======================= kernel 2: amax EMA finalize =======================
__global__ void finalize_amax_kernel(
    const float* __restrict__ in_amax, const float* __restrict__ w_amax,
    const unsigned int* __restrict__ bits, float* __restrict__ tail)
{
    if (threadIdx.x == 0) {
        float ax = __uint_as_float(bits[0]);
        float aw = __uint_as_float(bits[1]);
        if (!(ax == ax)) ax = AMAX_EPS_F;
        if (isinf(ax))   ax = FP8_MAX_F;
        if (!(aw == aw)) aw = AMAX_EPS_F;
        if (isinf(aw))   aw = FP8_MAX_F;
        tail[0] = fmaxf(fmaxf(__ldg(in_amax) * MOMENTUM_F, ax), AMAX_EPS_F);
        tail[1] = fmaxf(fmaxf(__ldg(w_amax)  * MOMENTUM_F, aw), AMAX_EPS_F);
    }
}

// ======================= GEMM: bf16 HMMA + ldmatrix, 2 CTA/SM =======================
static constexpr int BM = 128, BN = 128, BK = 64, NSTAGE = 3;
static constexpr int NKT = K_DIM / BK;                  // 64
static constexpr int ROWB = BK * 2;                     // 128 B per smem row
static constexpr int A_TILE_BYTES = BM * ROWB;          // 16384
static constexpr int B_TILE_BYTES = BN * ROWB;          // 16384
static constexpr int STAGE_BYTES  = A_TILE_BYTES + B_TILE_BYTES;  // 32768
static constexpr int SMEM_TOTAL   = NSTAGE * STAGE_BYTES;         // 98304

// one BK=64 slab of A(128 rows) + B(128 rows), SW128-swizzled, 256 threads
DEV_INLINE void load_stage(uint32_t sA, const __nv_bfloat16* gA,
                           const __nv_bfloat16* gB, int kt, int tid)
{
    const char* pA = (const char*)gA + (size_t)kt * ROWB;
    const char* pB = (const char*)gB + (size_t)kt * ROWB;
    #pragma unroll
    for (int i = 0; i < 4; i++) {                 // A: 1024 16B-chunks
        int chunk = tid + i * 256;
        int row = chunk >> 3, colb = (chunk & 7) << 4;
        cp_async16(sA + sw128((uint32_t)(row * ROWB + colb)),
                   pA + (size_t)row * K_BYTES + colb);
    }
    const uint32_t sB = sA + A_TILE_BYTES;
    #pragma unroll
    for (int i = 0; i < 4; i++) {                 // B: 1024 16B-chunks
        int chunk = tid + i * 256;
        int row = chunk >> 3, colb = (chunk & 7) << 4;
        cp_async16(sB + sw128((uint32_t)(row * ROWB + colb)),
                   pB + (size_t)row * K_BYTES + colb);
    }
    asm volatile("cp.async.commit_group;\n" ::: "memory");
}

__global__ void __launch_bounds__(256, 2)
gemm_kernel(float* __restrict__ out,
            const __nv_bfloat16* __restrict__ Aq, const __nv_bfloat16* __restrict__ Bq,
            const float* __restrict__ bias,
            const float* __restrict__ in_amax, const float* __restrict__ w_amax)
{
    extern __shared__ char smem[];
    const uint32_t sbase = smem_u32(smem);
    const int tid = threadIdx.x, wid = tid >> 5, lid = tid & 31;
    const int wm = wid >> 2, wn = wid & 3;        // 2x4 warp grid, tile 64x32
    const int bn = blockIdx.x, bm = blockIdx.y;

    const __nv_bfloat16* gA = Aq + (size_t)bm * BM * K_DIM;
    const __nv_bfloat16* gB = Bq + (size_t)bn * BN * K_DIM;

    float acc[4][4][4];
    #pragma unroll
    for (int mf = 0; mf < 4; mf++)
        #pragma unroll
        for (int nf = 0; nf < 4; nf++)
            #pragma unroll
            for (int q = 0; q < 4; q++) acc[mf][nf][q] = 0.0f;

    #pragma unroll
    for (int s = 0; s < NSTAGE; s++)
        load_stage(sbase + s * STAGE_BYTES, gA, gB, s, tid);

    // ldmatrix lane-address invariants
    // A x4 tiles: (m0-7,klo)(m8-15,klo)(m0-7,khi)(m8-15,khi) -> a0..a3
    const int a_row = wm * 64 + (lid & 7) + ((lid >> 3) & 1) * 8;   // + mf*16
    const int a_cbl = (lid >> 4) << 4;
    // B x4 tiles: (nf0,klo)(nf0,khi)(nf1,klo)(nf1,khi)
    const int b_row = wn * 32 + ((lid >> 4) << 3) + (lid & 7);      // + p*16
    const int b_cbl = ((lid >> 3) & 1) << 4;

    for (int kt = 0; kt < NKT; ++kt) {
        if (kt < NKT - 2)       asm volatile("cp.async.wait_group 2;\n" ::: "memory");
        else if (kt == NKT - 2) asm volatile("cp.async.wait_group 1;\n" ::: "memory");
        else                    asm volatile("cp.async.wait_group 0;\n" ::: "memory");
        __syncthreads();

        const uint32_t stA = sbase + (kt % NSTAGE) * STAGE_BYTES;
        const uint32_t stB = stA + A_TILE_BYTES;

        #pragma unroll
        for (int ks = 0; ks < 4; ks++) {          // 4 x k16 within BK=64
            const int cb = ks * 32;
            uint32_t a[4][4], b[4][4];
            #pragma unroll
            for (int p = 0; p < 2; p++) {
                uint32_t off = (uint32_t)((b_row + p * 16) * ROWB + cb + b_cbl);
                ldsm_x4(b[p * 2], stB + sw128(off));
            }
            #pragma unroll
            for (int mf = 0; mf < 4; mf++) {
                uint32_t off = (uint32_t)((a_row + mf * 16) * ROWB + cb + a_cbl);
                ldsm_x4(a[mf], stA + sw128(off));
            }
            #pragma unroll
            for (int mf = 0; mf < 4; mf++) {
                #pragma unroll
                for (int p = 0; p < 2; p++) {
                    mma_bf16(acc[mf][p * 2 + 0], a[mf], &b[p * 2][0]);
                    mma_bf16(acc[mf][p * 2 + 1], a[mf], &b[p * 2][2]);
                }
            }
        }
        __syncthreads();
        if (kt + NSTAGE < NKT)
            load_stage(sbase + (kt % NSTAGE) * STAGE_BYTES, gA, gB, kt + NSTAGE, tid);
    }

    // ---- epilogue: D * (ax*aw/448^2) + bias ----
    const float ax = fmaxf(__ldg(in_amax), AMAX_EPS_F);
    const float aw = fmaxf(__ldg(w_amax), AMAX_EPS_F);
    const float inv = (ax * aw) * (1.0f / (FP8_MAX_F * FP8_MAX_F));

    #pragma unroll
    for (int mf = 0; mf < 4; mf++) {
        const int r0 = bm * BM + wm * 64 + mf * 16 + (lid >> 2);
        #pragma unroll
        for (int nf = 0; nf < 4; nf++) {
            const int col = bn * BN + wn * 32 + nf * 8 + (lid & 3) * 2;
            const float b0 = __ldg(bias + col), b1 = __ldg(bias + col + 1);
            float2 v0 = {acc[mf][nf][0] * inv + b0, acc[mf][nf][1] * inv + b1};
            float2 v1 = {acc[mf][nf][2] * inv + b0, acc[mf][nf][3] * inv + b1};
            *reinterpret_cast<float2*>(out + (size_t)r0 * N_DIM + col) = v0;
            *reinterpret_cast<float2*>(out + (size_t)(r0 + 8) * N_DIM + col) = v1;
        }
    }
}

// ======================= launch =======================
extern "C" void kernel_launch(void* const* d_in, const int* in_sizes, int n_in,
                              void* d_out, int out_size)
{
    const float* x       = (const float*)d_in[0];
    const float* w       = (const float*)d_in[1];
    const float* bias    = (const float*)d_in[2];
    const float* in_amax = (const float*)d_in[3];
    const float* w_amax  = (const float*)d_in[4];
    float* out = (float*)d_out;

    __nv_bfloat16 *xq, *wq;
    unsigned int* ab;
    cudaGetSymbolAddress((void**)&xq, g_xq);
    cudaGetSymbolAddress((void**)&wq, g_wq);
    cudaGetSymbolAddress((void**)&ab, g_amax_bits);

    cudaFuncSetAttribute(gemm_kernel,
                         cudaFuncAttributeMaxDynamicSharedMemorySize, SMEM_TOTAL);

    init_amax_kernel<<<1, 32>>>(ab);
    quant_kernel<<<(M_DIM * K_DIM / 8) / 256, 256>>>(x, xq, in_amax, ab + 0);
    quant_kernel<<<(N_DIM * K_DIM / 8) / 256, 256>>>(w, wq, w_amax, ab + 1);
    finalize_amax_kernel<<<1, 32>>>(in_amax, w_amax, ab,
                                    out + (size_t)M_DIM * N_DIM);

    dim3 grid(N_DIM / BN, M_DIM / BM);   // (32, 64)
    gemm_kernel<<<grid, 256, SMEM_TOTAL>>>(out, xq, wq, bias, in_amax, w_amax);
}

// round 9
// speedup vs baseline: 1.3839x; 1.0028x over previous
#include <cuda_runtime.h>
#include <cuda_bf16.h>
#include <cstdint>

#define DEV_INLINE __device__ __forceinline__

static constexpr int M_DIM = 8192;
static constexpr int N_DIM = 4096;
static constexpr int K_DIM = 4096;
static constexpr int K_BYTES = K_DIM * 2;

static constexpr float FP8_MAX_F  = 448.0f;
static constexpr float AMAX_EPS_F = 1e-8f;
static constexpr float MOMENTUM_F = 0.95f;

// -------- scratch (allocation-free: device globals) --------
__device__ __align__(16) __nv_bfloat16 g_xq[(size_t)M_DIM * K_DIM];  // 64 MB
__device__ __align__(16) __nv_bfloat16 g_wq[(size_t)N_DIM * K_DIM];  // 32 MB
__device__ unsigned int g_amax_bits[2];

// ======================= helpers =======================
DEV_INLINE uint32_t smem_u32(const void* p) {
    uint32_t r;
    asm("{ .reg .u64 t; cvta.to.shared.u64 t, %1; cvt.u32.u64 %0, t; }" : "=r"(r) : "l"(p));
    return r;
}
DEV_INLINE void cp_async16(uint32_t smem, const void* gmem) {
    asm volatile("cp.async.cg.shared.global [%0], [%1], 16;\n" :: "r"(smem), "l"(gmem));
}
DEV_INLINE uint32_t sw128(uint32_t off) { return off ^ ((off >> 3) & 0x70); }

DEV_INLINE void ldsm_x4(uint32_t* r, uint32_t addr) {
    asm volatile("ldmatrix.sync.aligned.m8n8.x4.shared.b16 {%0,%1,%2,%3}, [%4];"
        : "=r"(r[0]), "=r"(r[1]), "=r"(r[2]), "=r"(r[3]) : "r"(addr));
}
DEV_INLINE void mma_bf16(float* c, const uint32_t* a, const uint32_t* b) {
    asm volatile(
        "mma.sync.aligned.m16n8k16.row.col.f32.bf16.bf16.f32 "
        "{%0,%1,%2,%3}, {%4,%5,%6,%7}, {%8,%9}, {%0,%1,%2,%3};"
        : "+f"(c[0]), "+f"(c[1]), "+f"(c[2]), "+f"(c[3])
        : "r"(a[0]), "r"(a[1]), "r"(a[2]), "r"(a[3]), "r"(b[0]), "r"(b[1]));
}

// ======================= kernel 0: init amax scratch =======================
__global__ void init_amax_kernel(unsigned int* bits) {
    if (threadIdx.x < 2) bits[threadIdx.x] = 0u;
}

// ======================= kernel 1: quantize + amax =======================
// fp32 -> scale -> e4m3 (rn.satfinite, exact ref semantics) -> bf16 (exact).
// Stores scaled-domain q values; epilogue multiplies by (ax*aw)/448^2.
__global__ void __launch_bounds__(256) quant_kernel(
    const float* __restrict__ in, __nv_bfloat16* __restrict__ outq,
    const float* __restrict__ amax_in, unsigned int* __restrict__ amax_bits)
{
    const int idx = blockIdx.x * blockDim.x + threadIdx.x;
    const float scale = FP8_MAX_F / fmaxf(__ldg(amax_in), AMAX_EPS_F);

    const float4* p = reinterpret_cast<const float4*>(in) + (size_t)idx * 2;
    float4 v0 = p[0], v1 = p[1];
    float vals[8] = {v0.x, v0.y, v0.z, v0.w, v1.x, v1.y, v1.z, v1.w};

    float m = 0.0f;
    #pragma unroll
    for (int i = 0; i < 8; i++) m = fmaxf(m, fabsf(vals[i]));

    uint32_t packed[4];
    #pragma unroll
    for (int i = 0; i < 4; i++) {
        unsigned short e;
        asm("cvt.rn.satfinite.e4m3x2.f32 %0, %1, %2;"
            : "=h"(e) : "f"(vals[2*i+1] * scale), "f"(vals[2*i] * scale));
        uint32_t h2;
        asm("cvt.rn.f16x2.e4m3x2 %0, %1;" : "=r"(h2) : "h"(e));
        float flo, fhi;
        asm("{ .reg .f16 a, b; mov.b32 {a, b}, %2; cvt.f32.f16 %0, a; cvt.f32.f16 %1, b; }"
            : "=f"(flo), "=f"(fhi) : "r"(h2));
        asm("cvt.rn.bf16x2.f32 %0, %1, %2;" : "=r"(packed[i]) : "f"(fhi), "f"(flo));
    }
    uint4 outv = {packed[0], packed[1], packed[2], packed[3]};
    reinterpret_cast<uint4*>(outq)[idx] = outv;

    #pragma unroll
    for (int o = 16; o > 0; o >>= 1) m = fmaxf(m, __shfl_xor_sync(0xffffffff, m, o));
    __shared__ float wmax[8];
    if ((threadIdx.x & 31) == 0) wmax[threadIdx.x >> 5] = m;
    __syncthreads();
    if (threadIdx.x == 0) {
        float t = wmax[0];
        #pragma unroll
        for (int i = 1; i < 8; i++) t = fmaxf(t, wmax[i]);
        atomicMax(amax_bits, __float_as_uint(t));
    }
}

// ======================= kernel 2: amax EMA finalize =======================
__global__ void finalize_amax_kernel(
    const float* __restrict__ in_amax, const float* __restrict__ w_amax,
    const unsigned int* __restrict__ bits, float* __restrict__ tail)
{
    if (threadIdx.x == 0) {
        float ax = __uint_as_float(bits[0]);
        float aw = __uint_as_float(bits[1]);
        if (!(ax == ax)) ax = AMAX_EPS_F;
        if (isinf(ax))   ax = FP8_MAX_F;
        if (!(aw == aw)) aw = AMAX_EPS_F;
        if (isinf(aw))   aw = FP8_MAX_F;
        tail[0] = fmaxf(fmaxf(__ldg(in_amax) * MOMENTUM_F, ax), AMAX_EPS_F);
        tail[1] = fmaxf(fmaxf(__ldg(w_amax)  * MOMENTUM_F, aw), AMAX_EPS_F);
    }
}

// ======================= GEMM: bf16 HMMA, single-barrier pipeline =======================
static constexpr int BM = 128, BN = 128, BK = 64, NSTAGE = 3;
static constexpr int NKT = K_DIM / BK;                  // 64
static constexpr int ROWB = BK * 2;                     // 128 B per smem row
static constexpr int A_TILE_BYTES = BM * ROWB;          // 16384
static constexpr int B_TILE_BYTES = BN * ROWB;          // 16384
static constexpr int STAGE_BYTES  = A_TILE_BYTES + B_TILE_BYTES;  // 32768
static constexpr int SMEM_TOTAL   = NSTAGE * STAGE_BYTES;         // 98304

// one BK=64 slab of A(128 rows) + B(128 rows), SW128-swizzled, 256 threads
DEV_INLINE void load_stage(uint32_t sA, const __nv_bfloat16* gA,
                           const __nv_bfloat16* gB, int kt, int tid)
{
    const char* pA = (const char*)gA + (size_t)kt * ROWB;
    const char* pB = (const char*)gB + (size_t)kt * ROWB;
    #pragma unroll
    for (int i = 0; i < 4; i++) {                 // A: 1024 16B-chunks
        int chunk = tid + i * 256;
        int row = chunk >> 3, colb = (chunk & 7) << 4;
        cp_async16(sA + sw128((uint32_t)(row * ROWB + colb)),
                   pA + (size_t)row * K_BYTES + colb);
    }
    const uint32_t sB = sA + A_TILE_BYTES;
    #pragma unroll
    for (int i = 0; i < 4; i++) {                 // B: 1024 16B-chunks
        int chunk = tid + i * 256;
        int row = chunk >> 3, colb = (chunk & 7) << 4;
        cp_async16(sB + sw128((uint32_t)(row * ROWB + colb)),
                   pB + (size_t)row * K_BYTES + colb);
    }
    asm volatile("cp.async.commit_group;\n" ::: "memory");
}

__global__ void __launch_bounds__(256, 2)
gemm_kernel(float* __restrict__ out,
            const __nv_bfloat16* __restrict__ Aq, const __nv_bfloat16* __restrict__ Bq,
            const float* __restrict__ bias,
            const float* __restrict__ in_amax, const float* __restrict__ w_amax)
{
    extern __shared__ char smem[];
    const uint32_t sbase = smem_u32(smem);
    const int tid = threadIdx.x, wid = tid >> 5, lid = tid & 31;
    const int wm = wid >> 2, wn = wid & 3;        // 2x4 warp grid, tile 64x32
    const int bn = blockIdx.x, bm = blockIdx.y;

    const __nv_bfloat16* gA = Aq + (size_t)bm * BM * K_DIM;
    const __nv_bfloat16* gB = Bq + (size_t)bn * BN * K_DIM;

    float acc[4][4][4];
    #pragma unroll
    for (int mf = 0; mf < 4; mf++)
        #pragma unroll
        for (int nf = 0; nf < 4; nf++)
            #pragma unroll
            for (int q = 0; q < 4; q++) acc[mf][nf][q] = 0.0f;

    // depth-2 prefetch: slabs 0 and 1 into stages 0, 1 (stage 2 free)
    load_stage(sbase + 0 * STAGE_BYTES, gA, gB, 0, tid);
    load_stage(sbase + 1 * STAGE_BYTES, gA, gB, 1, tid);

    // ldmatrix lane-address invariants
    // A x4 tiles: (m0-7,klo)(m8-15,klo)(m0-7,khi)(m8-15,khi) -> a0..a3
    const int a_row = wm * 64 + (lid & 7) + ((lid >> 3) & 1) * 8;   // + mf*16
    const int a_cbl = (lid >> 4) << 4;
    // B x4 tiles: (nf0,klo)(nf0,khi)(nf1,klo)(nf1,khi)
    const int b_row = wn * 32 + ((lid >> 4) << 3) + (lid & 7);      // + p*16
    const int b_cbl = ((lid >> 3) & 1) << 4;

    for (int kt = 0; kt < NKT; ++kt) {
        // slab kt landed?
        if (kt < NKT - 1) asm volatile("cp.async.wait_group 1;\n" ::: "memory");
        else              asm volatile("cp.async.wait_group 0;\n" ::: "memory");
        // single barrier: data visible to all + everyone finished slab kt-1,
        // whose stage (kt+2)%3 is exactly the refill target below.
        __syncthreads();

        if (kt + 2 < NKT)
            load_stage(sbase + ((kt + 2) % NSTAGE) * STAGE_BYTES, gA, gB, kt + 2, tid);

        const uint32_t stA = sbase + (kt % NSTAGE) * STAGE_BYTES;
        const uint32_t stB = stA + A_TILE_BYTES;

        #pragma unroll
        for (int ks = 0; ks < 4; ks++) {          // 4 x k16 within BK=64
            const int cb = ks * 32;
            uint32_t a[4][4], b[4][4];
            #pragma unroll
            for (int p = 0; p < 2; p++) {
                uint32_t off = (uint32_t)((b_row + p * 16) * ROWB + cb + b_cbl);
                ldsm_x4(b[p * 2], stB + sw128(off));
            }
            #pragma unroll
            for (int mf = 0; mf < 4; mf++) {
                uint32_t off = (uint32_t)((a_row + mf * 16) * ROWB + cb + a_cbl);
                ldsm_x4(a[mf], stA + sw128(off));
            }
            #pragma unroll
            for (int mf = 0; mf < 4; mf++) {
                #pragma unroll
                for (int p = 0; p < 2; p++) {
                    mma_bf16(acc[mf][p * 2 + 0], a[mf], &b[p * 2][0]);
                    mma_bf16(acc[mf][p * 2 + 1], a[mf], &b[p * 2][2]);
                }
            }
        }
    }

    // ---- epilogue: D * (ax*aw/448^2) + bias ----
    const float ax = fmaxf(__ldg(in_amax), AMAX_EPS_F);
    const float aw = fmaxf(__ldg(w_amax), AMAX_EPS_F);
    const float inv = (ax * aw) * (1.0f / (FP8_MAX_F * FP8_MAX_F));

    float bcol[4][2];
    #pragma unroll
    for (int nf = 0; nf < 4; nf++) {
        const int col = bn * BN + wn * 32 + nf * 8 + (lid & 3) * 2;
        bcol[nf][0] = __ldg(bias + col);
        bcol[nf][1] = __ldg(bias + col + 1);
    }

    #pragma unroll
    for (int mf = 0; mf < 4; mf++) {
        const int r0 = bm * BM + wm * 64 + mf * 16 + (lid >> 2);
        #pragma unroll
        for (int nf = 0; nf < 4; nf++) {
            const int col = bn * BN + wn * 32 + nf * 8 + (lid & 3) * 2;
            float2 v0 = {acc[mf][nf][0] * inv + bcol[nf][0],
                         acc[mf][nf][1] * inv + bcol[nf][1]};
            float2 v1 = {acc[mf][nf][2] * inv + bcol[nf][0],
                         acc[mf][nf][3] * inv + bcol[nf][1]};
            *reinterpret_cast<float2*>(out + (size_t)r0 * N_DIM + col) = v0;
            *reinterpret_cast<float2*>(out + (size_t)(r0 + 8) * N_DIM + col) = v1;
        }
    }
}

// ======================= launch =======================
extern "C" void kernel_launch(void* const* d_in, const int* in_sizes, int n_in,
                              void* d_out, int out_size)
{
    const float* x       = (const float*)d_in[0];
    const float* w       = (const float*)d_in[1];
    const float* bias    = (const float*)d_in[2];
    const float* in_amax = (const float*)d_in[3];
    const float* w_amax  = (const float*)d_in[4];
    float* out = (float*)d_out;

    __nv_bfloat16 *xq, *wq;
    unsigned int* ab;
    cudaGetSymbolAddress((void**)&xq, g_xq);
    cudaGetSymbolAddress((void**)&wq, g_wq);
    cudaGetSymbolAddress((void**)&ab, g_amax_bits);

    cudaFuncSetAttribute(gemm_kernel,
                         cudaFuncAttributeMaxDynamicSharedMemorySize, SMEM_TOTAL);

    init_amax_kernel<<<1, 32>>>(ab);
    quant_kernel<<<(M_DIM * K_DIM / 8) / 256, 256>>>(x, xq, in_amax, ab + 0);
    quant_kernel<<<(N_DIM * K_DIM / 8) / 256, 256>>>(w, wq, w_amax, ab + 1);
    finalize_amax_kernel<<<1, 32>>>(in_amax, w_amax, ab,
                                    out + (size_t)M_DIM * N_DIM);

    dim3 grid(N_DIM / BN, M_DIM / BM);   // (32, 64)
    gemm_kernel<<<grid, 256, SMEM_TOTAL>>>(out, xq, wq, bias, in_amax, w_amax);
}

// round 10
// speedup vs baseline: 1.3916x; 1.0056x over previous
#include <cuda_runtime.h>
#include <cuda_bf16.h>
#include <cstdint>

#define DEV_INLINE __device__ __forceinline__

static constexpr int M_DIM = 8192;
static constexpr int N_DIM = 4096;
static constexpr int K_DIM = 4096;
static constexpr int K_BYTES = K_DIM * 2;

static constexpr float FP8_MAX_F  = 448.0f;
static constexpr float AMAX_EPS_F = 1e-8f;
static constexpr float MOMENTUM_F = 0.95f;

// -------- scratch (allocation-free: device globals, zero-initialized) --------
__device__ __align__(16) __nv_bfloat16 g_xq[(size_t)M_DIM * K_DIM];  // 64 MB
__device__ __align__(16) __nv_bfloat16 g_wq[(size_t)N_DIM * K_DIM];  // 32 MB
__device__ unsigned int g_amax_bits[2];   // starts 0; finalize resets to 0 each call

// ======================= helpers =======================
DEV_INLINE uint32_t smem_u32(const void* p) {
    uint32_t r;
    asm("{ .reg .u64 t; cvta.to.shared.u64 t, %1; cvt.u32.u64 %0, t; }" : "=r"(r) : "l"(p));
    return r;
}
DEV_INLINE void cp_async16(uint32_t smem, const void* gmem) {
    asm volatile("cp.async.cg.shared.global [%0], [%1], 16;\n" :: "r"(smem), "l"(gmem));
}
DEV_INLINE uint32_t sw128(uint32_t off) { return off ^ ((off >> 3) & 0x70); }

DEV_INLINE void ldsm_x4(uint32_t* r, uint32_t addr) {
    asm volatile("ldmatrix.sync.aligned.m8n8.x4.shared.b16 {%0,%1,%2,%3}, [%4];"
        : "=r"(r[0]), "=r"(r[1]), "=r"(r[2]), "=r"(r[3]) : "r"(addr));
}
DEV_INLINE void mma_bf16(float* c, const uint32_t* a, const uint32_t* b) {
    asm volatile(
        "mma.sync.aligned.m16n8k16.row.col.f32.bf16.bf16.f32 "
        "{%0,%1,%2,%3}, {%4,%5,%6,%7}, {%8,%9}, {%0,%1,%2,%3};"
        : "+f"(c[0]), "+f"(c[1]), "+f"(c[2]), "+f"(c[3])
        : "r"(a[0]), "r"(a[1]), "r"(a[2]), "r"(a[3]), "r"(b[0]), "r"(b[1]));
}

// ======================= kernel 1: combined quantize + amax =======================
// Blocks [0, XBLK) process x -> g_xq (amax slot 0); the rest process w -> g_wq (slot 1).
static constexpr int XBLK = (M_DIM * K_DIM / 8) / 256;   // 16384
static constexpr int WBLK = (N_DIM * K_DIM / 8) / 256;   // 8192

__global__ void __launch_bounds__(256) quant_kernel(
    const float* __restrict__ x, const float* __restrict__ w,
    const float* __restrict__ in_amax, const float* __restrict__ w_amax,
    unsigned int* __restrict__ amax_bits)
{
    const bool is_x = (blockIdx.x < XBLK);
    const float* in = is_x ? x : w;
    __nv_bfloat16* outq = is_x ? g_xq : g_wq;
    const int bid = is_x ? blockIdx.x : (blockIdx.x - XBLK);
    const int idx = bid * blockDim.x + threadIdx.x;
    const float amax_v = is_x ? __ldg(in_amax) : __ldg(w_amax);
    const float scale = FP8_MAX_F / fmaxf(amax_v, AMAX_EPS_F);

    const float4* p = reinterpret_cast<const float4*>(in) + (size_t)idx * 2;
    float4 v0 = p[0], v1 = p[1];
    float vals[8] = {v0.x, v0.y, v0.z, v0.w, v1.x, v1.y, v1.z, v1.w};

    float m = 0.0f;
    #pragma unroll
    for (int i = 0; i < 8; i++) m = fmaxf(m, fabsf(vals[i]));

    uint32_t packed[4];
    #pragma unroll
    for (int i = 0; i < 4; i++) {
        unsigned short e;
        asm("cvt.rn.satfinite.e4m3x2.f32 %0, %1, %2;"
            : "=h"(e) : "f"(vals[2*i+1] * scale), "f"(vals[2*i] * scale));
        uint32_t h2;
        asm("cvt.rn.f16x2.e4m3x2 %0, %1;" : "=r"(h2) : "h"(e));
        float flo, fhi;
        asm("{ .reg .f16 a, b; mov.b32 {a, b}, %2; cvt.f32.f16 %0, a; cvt.f32.f16 %1, b; }"
            : "=f"(flo), "=f"(fhi) : "r"(h2));
        asm("cvt.rn.bf16x2.f32 %0, %1, %2;" : "=r"(packed[i]) : "f"(fhi), "f"(flo));
    }
    uint4 outv = {packed[0], packed[1], packed[2], packed[3]};
    reinterpret_cast<uint4*>(outq)[idx] = outv;

    #pragma unroll
    for (int o = 16; o > 0; o >>= 1) m = fmaxf(m, __shfl_xor_sync(0xffffffff, m, o));
    __shared__ float wmax[8];
    if ((threadIdx.x & 31) == 0) wmax[threadIdx.x >> 5] = m;
    __syncthreads();
    if (threadIdx.x == 0) {
        float t = wmax[0];
        #pragma unroll
        for (int i = 1; i < 8; i++) t = fmaxf(t, wmax[i]);
        atomicMax(amax_bits + (is_x ? 0 : 1), __float_as_uint(t));
    }
}

// ======================= kernel 2: amax EMA finalize (+ scratch reset) =======================
__global__ void finalize_amax_kernel(
    const float* __restrict__ in_amax, const float* __restrict__ w_amax,
    unsigned int* __restrict__ bits, float* __restrict__ tail)
{
    if (threadIdx.x == 0) {
        float ax = __uint_as_float(bits[0]);
        float aw = __uint_as_float(bits[1]);
        if (!(ax == ax)) ax = AMAX_EPS_F;
        if (isinf(ax))   ax = FP8_MAX_F;
        if (!(aw == aw)) aw = AMAX_EPS_F;
        if (isinf(aw))   aw = FP8_MAX_F;
        tail[0] = fmaxf(fmaxf(__ldg(in_amax) * MOMENTUM_F, ax), AMAX_EPS_F);
        tail[1] = fmaxf(fmaxf(__ldg(w_amax)  * MOMENTUM_F, aw), AMAX_EPS_F);
        // reset scratch so every kernel_launch call starts from identical state
        bits[0] = 0u;
        bits[1] = 0u;
    }
}

// ======================= GEMM: bf16 HMMA, single-barrier pipeline =======================
static constexpr int BM = 128, BN = 128, BK = 64, NSTAGE = 3;
static constexpr int NKT = K_DIM / BK;                  // 64
static constexpr int ROWB = BK * 2;                     // 128 B per smem row
static constexpr int A_TILE_BYTES = BM * ROWB;          // 16384
static constexpr int B_TILE_BYTES = BN * ROWB;          // 16384
static constexpr int STAGE_BYTES  = A_TILE_BYTES + B_TILE_BYTES;  // 32768
static constexpr int SMEM_TOTAL   = NSTAGE * STAGE_BYTES;         // 98304

DEV_INLINE void load_stage(uint32_t sA, const __nv_bfloat16* gA,
                           const __nv_bfloat16* gB, int kt, int tid)
{
    const char* pA = (const char*)gA + (size_t)kt * ROWB;
    const char* pB = (const char*)gB + (size_t)kt * ROWB;
    #pragma unroll
    for (int i = 0; i < 4; i++) {
        int chunk = tid + i * 256;
        int row = chunk >> 3, colb = (chunk & 7) << 4;
        cp_async16(sA + sw128((uint32_t)(row * ROWB + colb)),
                   pA + (size_t)row * K_BYTES + colb);
    }
    const uint32_t sB = sA + A_TILE_BYTES;
    #pragma unroll
    for (int i = 0; i < 4; i++) {
        int chunk = tid + i * 256;
        int row = chunk >> 3, colb = (chunk & 7) << 4;
        cp_async16(sB + sw128((uint32_t)(row * ROWB + colb)),
                   pB + (size_t)row * K_BYTES + colb);
    }
    asm volatile("cp.async.commit_group;\n" ::: "memory");
}

__global__ void __launch_bounds__(256, 2)
gemm_kernel(float* __restrict__ out,
            const __nv_bfloat16* __restrict__ Aq, const __nv_bfloat16* __restrict__ Bq,
            const float* __restrict__ bias,
            const float* __restrict__ in_amax, const float* __restrict__ w_amax)
{
    extern __shared__ char smem[];
    const uint32_t sbase = smem_u32(smem);
    const int tid = threadIdx.x, wid = tid >> 5, lid = tid & 31;
    const int wm = wid >> 2, wn = wid & 3;        // 2x4 warp grid, tile 64x32
    const int bn = blockIdx.x, bm = blockIdx.y;

    const __nv_bfloat16* gA = Aq + (size_t)bm * BM * K_DIM;
    const __nv_bfloat16* gB = Bq + (size_t)bn * BN * K_DIM;

    float acc[4][4][4];
    #pragma unroll
    for (int mf = 0; mf < 4; mf++)
        #pragma unroll
        for (int nf = 0; nf < 4; nf++)
            #pragma unroll
            for (int q = 0; q < 4; q++) acc[mf][nf][q] = 0.0f;

    load_stage(sbase + 0 * STAGE_BYTES, gA, gB, 0, tid);
    load_stage(sbase + 1 * STAGE_BYTES, gA, gB, 1, tid);

    // ldmatrix lane-address invariants
    const int a_row = wm * 64 + (lid & 7) + ((lid >> 3) & 1) * 8;   // + mf*16
    const int a_cbl = (lid >> 4) << 4;
    const int b_row = wn * 32 + ((lid >> 4) << 3) + (lid & 7);      // + p*16
    const int b_cbl = ((lid >> 3) & 1) << 4;

    for (int kt = 0; kt < NKT; ++kt) {
        if (kt < NKT - 1) asm volatile("cp.async.wait_group 1;\n" ::: "memory");
        else              asm volatile("cp.async.wait_group 0;\n" ::: "memory");
        __syncthreads();   // slab kt visible; stage (kt+2)%3 free for refill

        if (kt + 2 < NKT)
            load_stage(sbase + ((kt + 2) % NSTAGE) * STAGE_BYTES, gA, gB, kt + 2, tid);

        const uint32_t stA = sbase + (kt % NSTAGE) * STAGE_BYTES;
        const uint32_t stB = stA + A_TILE_BYTES;

        // B double-buffer across ks: bb[cur][p*2+..], 8 regs per buffer
        uint32_t bb[2][8];
        ldsm_x4(&bb[0][0], stB + sw128((uint32_t)((b_row +  0) * ROWB + b_cbl)));
        ldsm_x4(&bb[0][4], stB + sw128((uint32_t)((b_row + 16) * ROWB + b_cbl)));

        #pragma unroll
        for (int ks = 0; ks < 4; ks++) {
            const int cb = ks * 32;
            const int cur = ks & 1, nxt = cur ^ 1;
            uint32_t a[4][4];
            #pragma unroll
            for (int mf = 0; mf < 4; mf++) {
                uint32_t off = (uint32_t)((a_row + mf * 16) * ROWB + cb + a_cbl);
                ldsm_x4(a[mf], stA + sw128(off));
            }
            if (ks < 3) {
                const int cbn = cb + 32;
                ldsm_x4(&bb[nxt][0], stB + sw128((uint32_t)((b_row +  0) * ROWB + cbn + b_cbl)));
                ldsm_x4(&bb[nxt][4], stB + sw128((uint32_t)((b_row + 16) * ROWB + cbn + b_cbl)));
            }
            #pragma unroll
            for (int mf = 0; mf < 4; mf++) {
                mma_bf16(acc[mf][0], a[mf], &bb[cur][0]);   // nf0 (rows b_row+0 grp)
                mma_bf16(acc[mf][1], a[mf], &bb[cur][2]);   // nf1
                mma_bf16(acc[mf][2], a[mf], &bb[cur][4]);   // nf2 (rows b_row+16 grp)
                mma_bf16(acc[mf][3], a[mf], &bb[cur][6]);   // nf3
            }
        }
    }

    // ---- epilogue: D * (ax*aw/448^2) + bias ----
    const float ax = fmaxf(__ldg(in_amax), AMAX_EPS_F);
    const float aw = fmaxf(__ldg(w_amax), AMAX_EPS_F);
    const float inv = (ax * aw) * (1.0f / (FP8_MAX_F * FP8_MAX_F));

    float bcol[4][2];
    #pragma unroll
    for (int nf = 0; nf < 4; nf++) {
        const int col = bn * BN + wn * 32 + nf * 8 + (lid & 3) * 2;
        bcol[nf][0] = __ldg(bias + col);
        bcol[nf][1] = __ldg(bias + col + 1);
    }

    #pragma unroll
    for (int mf = 0; mf < 4; mf++) {
        const int r0 = bm * BM + wm * 64 + mf * 16 + (lid >> 2);
        #pragma unroll
        for (int nf = 0; nf < 4; nf++) {
            const int col = bn * BN + wn * 32 + nf * 8 + (lid & 3) * 2;
            float2 v0 = {acc[mf][nf][0] * inv + bcol[nf][0],
                         acc[mf][nf][1] * inv + bcol[nf][1]};
            float2 v1 = {acc[mf][nf][2] * inv + bcol[nf][0],
                         acc[mf][nf][3] * inv + bcol[nf][1]};
            *reinterpret_cast<float2*>(out + (size_t)r0 * N_DIM + col) = v0;
            *reinterpret_cast<float2*>(out + (size_t)(r0 + 8) * N_DIM + col) = v1;
        }
    }
}

// ======================= launch =======================
extern "C" void kernel_launch(void* const* d_in, const int* in_sizes, int n_in,
                              void* d_out, int out_size)
{
    const float* x       = (const float*)d_in[0];
    const float* w       = (const float*)d_in[1];
    const float* bias    = (const float*)d_in[2];
    const float* in_amax = (const float*)d_in[3];
    const float* w_amax  = (const float*)d_in[4];
    float* out = (float*)d_out;

    __nv_bfloat16 *xq, *wq;
    unsigned int* ab;
    cudaGetSymbolAddress((void**)&xq, g_xq);
    cudaGetSymbolAddress((void**)&wq, g_wq);
    cudaGetSymbolAddress((void**)&ab, g_amax_bits);

    cudaFuncSetAttribute(gemm_kernel,
                         cudaFuncAttributeMaxDynamicSharedMemorySize, SMEM_TOTAL);

    quant_kernel<<<XBLK + WBLK, 256>>>(x, w, in_amax, w_amax, ab);
    finalize_amax_kernel<<<1, 32>>>(in_amax, w_amax, ab,
                                    out + (size_t)M_DIM * N_DIM);

    dim3 grid(N_DIM / BN, M_DIM / BM);   // (32, 64)
    gemm_kernel<<<grid, 256, SMEM_TOTAL>>>(out, xq, wq, bias, in_amax, w_amax);
}